// round 15
// baseline (speedup 1.0000x reference)
#include <cuda_runtime.h>
#include <math.h>

// Problem constants (fixed shapes from reference: B=4, C=128, H=W=256)
constexpr int BDIM   = 512;
constexpr int NB     = 4096;          // histogram bins per level
constexpr int HW     = 65536;         // H*W
constexpr unsigned KSEL = 32768;      // k = 0.5*H*W
constexpr int CCH    = 128;
constexpr int BB     = 4;
constexpr int NSLICE = CCH * BB;      // 512 (c,b) slices
constexpr int CPT    = NB / BDIM;     // 8 bins per thread in select scans

__device__ double g_S[NSLICE];                  // total entropy sum per slice
__device__ double g_T[NSLICE];                  // top-k entropy sum per slice
__device__ unsigned int g_done = 0;             // CTA completion counter (reset each launch)

__device__ __forceinline__ unsigned key1_of(float e) {
    unsigned u = __float_as_uint(e);
    if (u & 0x80000000u) u = 0u;                 // negatives / -0.0 -> bin 0
    return min(u >> 18, (unsigned)(NB - 1));
}

__device__ __forceinline__ float ent_of(float x) {
    return fmaxf(-x * __logf(x), 0.0f);          // fmaxf kills NaN and -0.0
}

// midpoint value of level-2 bin i within level-1 bin b1 (bit-pattern reconstruction)
__device__ __forceinline__ float bin2_mid(unsigned b1, unsigned i) {
    return __uint_as_float((b1 << 18) | (i << 6) | 32u);
}

__device__ __forceinline__ double blockReduceD(double v, double* dred) {
    int lane = threadIdx.x & 31;
    int wid  = threadIdx.x >> 5;
    #pragma unroll
    for (int o = 16; o > 0; o >>= 1) v += __shfl_down_sync(0xffffffffu, v, o);
    if (lane == 0) dred[wid] = v;
    __syncthreads();
    double r;
    if (wid == 0) {
        r = (lane < BDIM / 32) ? dred[lane] : 0.0;
        #pragma unroll
        for (int o = 16; o > 0; o >>= 1) r += __shfl_down_sync(0xffffffffu, r, o);
        if (lane == 0) dred[0] = r;
    }
    __syncthreads();
    r = dred[0];
    __syncthreads();   // protect dred for reuse
    return r;
}

// Find bin b and cnt_gt = count(elements in bins > b) such that
// cnt_gt < k <= cnt_gt + hist[b].  Results broadcast via bcast[0]=b, bcast[1]=cnt_gt.
__device__ __forceinline__ void selectBin(const unsigned int* hist, unsigned int* chunk,
                                          unsigned int k, unsigned int* bcast) {
    const int t = threadIdx.x;
    const unsigned base = (unsigned)t * CPT;
    unsigned int ct = 0;
    #pragma unroll
    for (int i = 0; i < CPT; i++) ct += hist[base + i];
    chunk[t] = ct;
    // inclusive suffix sum over chunks (Kogge-Stone)
    for (int off = 1; off < BDIM; off <<= 1) {
        __syncthreads();
        unsigned int add = (t + off < BDIM) ? chunk[t + off] : 0u;
        __syncthreads();
        chunk[t] += add;
    }
    __syncthreads();
    unsigned int incl = chunk[t];
    unsigned int suf  = incl - ct;   // count strictly above this chunk
    if (suf < k && k <= incl) {      // exactly one thread matches
        unsigned int running = suf;
        #pragma unroll
        for (int i = CPT - 1; i >= 0; i--) {
            unsigned int c = hist[base + i];
            if (running < k && k <= running + c) {
                bcast[0] = base + (unsigned)i;
                bcast[1] = running;
                break;
            }
            running += c;
        }
    }
    __syncthreads();
}

__global__ void __launch_bounds__(BDIM)
k_main(const float* __restrict__ hsi, const float* __restrict__ wp,
       float* __restrict__ out) {
    __shared__ unsigned int s_hist[NB];     // 16 KB (level-1 counts, reused for level-2 counts)
    __shared__ unsigned int s_chunk[BDIM];  // 2 KB
    __shared__ double       s_dred[32];
    __shared__ unsigned int s_bcast[2];
    __shared__ int          s_last;

    const int t = threadIdx.x;
    const int s = blockIdx.x;                 // slice id (memory-linear: b = s/CCH, c = s%CCH)
    const float wv = wp[0];

    const float4* __restrict__ in = reinterpret_cast<const float4*>(hsi + (size_t)s * HW);

    if (t < 2) s_bcast[t] = 0u;
    for (int i = t; i < NB; i += BDIM) s_hist[i] = 0u;
    __syncthreads();

    // ---- Pass A: entropy (fast log) + float lane-sums + level-1 count hist ----
    float a0 = 0.f, a1 = 0.f, a2 = 0.f, a3 = 0.f;   // per-lane float accumulators (32 adds each)
    #pragma unroll 4
    for (int i = t; i < HW / 4; i += BDIM) {
        float4 v = in[i];
        float e0 = ent_of(v.x * wv);
        float e1 = ent_of(v.y * wv);
        float e2 = ent_of(v.z * wv);
        float e3 = ent_of(v.w * wv);
        a0 += e0; a1 += e1; a2 += e2; a3 += e3;
        atomicAdd(&s_hist[key1_of(e0)], 1u);
        atomicAdd(&s_hist[key1_of(e1)], 1u);
        atomicAdd(&s_hist[key1_of(e2)], 1u);
        atomicAdd(&s_hist[key1_of(e3)], 1u);
    }
    __syncthreads();

    double lsum = ((double)a0 + (double)a1) + ((double)a2 + (double)a3);
    double Ssum = blockReduceD(lsum, s_dred);

    // ---- Level-1 select ----
    selectBin(s_hist, s_chunk, KSEL, s_bcast);
    const unsigned b1      = s_bcast[0];
    const unsigned cnt_gt1 = s_bcast[1];
    __syncthreads();

    // clear for level-2 (count-only)
    for (int i = t; i < NB; i += BDIM) s_hist[i] = 0u;
    __syncthreads();

    // ---- Pass B: re-read input, recompute entropy (bit-identical), sum above b1;
    //      level-2 COUNT hist for boundary bin (values reconstructed from bin index) ----
    float g0 = 0.f, g1 = 0.f, g2 = 0.f, g3 = 0.f;
    #pragma unroll 4
    for (int i = t; i < HW / 4; i += BDIM) {
        float4 v = in[i];
        float e0 = ent_of(v.x * wv);
        float e1 = ent_of(v.y * wv);
        float e2 = ent_of(v.z * wv);
        float e3 = ent_of(v.w * wv);
        unsigned ka = key1_of(e0), kb = key1_of(e1);
        unsigned kc = key1_of(e2), kd = key1_of(e3);
        if (ka > b1) g0 += e0;
        else if (ka == b1) atomicAdd(&s_hist[(__float_as_uint(e0) >> 6) & (NB - 1)], 1u);
        if (kb > b1) g1 += e1;
        else if (kb == b1) atomicAdd(&s_hist[(__float_as_uint(e1) >> 6) & (NB - 1)], 1u);
        if (kc > b1) g2 += e2;
        else if (kc == b1) atomicAdd(&s_hist[(__float_as_uint(e2) >> 6) & (NB - 1)], 1u);
        if (kd > b1) g3 += e3;
        else if (kd == b1) atomicAdd(&s_hist[(__float_as_uint(e3) >> 6) & (NB - 1)], 1u);
    }
    __syncthreads();

    double sgt = ((double)g0 + (double)g1) + ((double)g2 + (double)g3);
    double SGT = blockReduceD(sgt, s_dred);

    // ---- Level-2 select ----
    const unsigned kp = KSEL - cnt_gt1;           // in [1, hist1[b1]]
    selectBin(s_hist, s_chunk, kp, s_bcast);
    const unsigned b2      = s_bcast[0];
    const unsigned cnt_gt2 = s_bcast[1];
    __syncthreads();

    // sum of level-2 bins strictly above b2, values = bin midpoints (<=32 ulp/elem error)
    double l2 = 0.0;
    for (int i = t; i < NB; i += BDIM)
        if ((unsigned)i > b2) l2 += (double)s_hist[i] * (double)bin2_mid(b1, (unsigned)i);
    double SGT2 = blockReduceD(l2, s_dred);

    if (t == 0) {
        unsigned r2 = kp - cnt_gt2;               // in [1, hist2[b2]]
        g_S[s] = Ssum;
        g_T[s] = SGT + SGT2 + (double)r2 * (double)bin2_mid(b1, b2);
    }

    // ---- Fused finalization: last CTA to finish reduces 128 channels ----
    __threadfence();
    if (t == 0) {
        unsigned old = atomicAdd(&g_done, 1u);
        s_last = (old == (unsigned)(NSLICE - 1)) ? 1 : 0;
    }
    __syncthreads();
    if (s_last) {
        __shared__ double d[CCH];
        __shared__ double sv[CCH];
        __shared__ int    si[CCH];
        if (t < CCH) {
            double S = 0.0, T = 0.0;
            #pragma unroll
            for (int b = 0; b < BB; b++) {
                S += g_S[b * CCH + t];
                T += g_T[b * CCH + t];
            }
            double mean      = S / ((double)BB * (double)HW);
            double mean_high = T / ((double)BB * (double)KSEL);
            d[t] = 2.0 * (mean_high - mean);
        }
        __syncthreads();
        #pragma unroll
        for (int j = 0; j < 3; j++) {
            if (t < CCH) { sv[t] = d[t]; si[t] = t; }
            __syncthreads();
            #pragma unroll
            for (int off = CCH / 2; off > 0; off >>= 1) {
                if (t < off) {
                    double ov = sv[t + off]; int oi = si[t + off];
                    // argsort(-delta) stable: larger value wins; on tie, lower index wins
                    if (ov > sv[t] || (ov == sv[t] && oi < si[t])) { sv[t] = ov; si[t] = oi; }
                }
                __syncthreads();
            }
            if (t == 0) {
                out[j] = (float)si[0];             // FLOAT32 output: indices as f32 values
                d[si[0]] = -1e300;
            }
            __syncthreads();
        }
        if (t == 0) g_done = 0;                    // reset for next graph replay
    }
}

extern "C" void kernel_launch(void* const* d_in, const int* in_sizes, int n_in,
                              void* d_out, int out_size) {
    // Robust input selection: hsi is the big tensor (16,777,216 elems), w is scalar.
    const float* hsi = (const float*)d_in[0];
    const float* w   = (n_in > 1) ? (const float*)d_in[1] : (const float*)d_in[0];
    if (n_in > 1 && in_sizes[0] < in_sizes[1]) {
        hsi = (const float*)d_in[1];
        w   = (const float*)d_in[0];
    }
    float* out = (float*)d_out;

    k_main<<<NSLICE, BDIM>>>(hsi, w, out);
}

// round 16
// speedup vs baseline: 1.2756x; 1.2756x over previous
#include <cuda_runtime.h>
#include <math.h>

// Problem constants (fixed shapes from reference: B=4, C=128, H=W=256)
constexpr int BDIM   = 256;
constexpr int NB1    = 4096;          // coarse histogram bins (sampled, level-1)
constexpr int WIN    = 5;             // coarse-bin window width
constexpr int SUBB   = 1024;          // sub-bins per coarse bin (level-2)
constexpr int NB2    = WIN * SUBB;    // 5120 exact window bins
constexpr int HW     = 65536;         // H*W
constexpr unsigned KSEL = 32768;      // k = 0.5*H*W
constexpr unsigned KSUB = 4096;       // sample target: 8192 samples * (k/HW)
constexpr int CCH    = 128;
constexpr int BB     = 4;
constexpr int NSLICE = CCH * BB;      // 512 (c,b) slices

__device__ double g_S[NSLICE];                  // total entropy sum per slice
__device__ double g_T[NSLICE];                  // top-k entropy sum per slice
__device__ unsigned int g_done = 0;             // CTA completion counter

__device__ __forceinline__ float ent_of(float x) {
    return fmaxf(-x * __logf(x), 0.0f);          // kills NaN and -0.0; e >= 0
}
__device__ __forceinline__ unsigned key1_of(float e) {
    return min(__float_as_uint(e) >> 18, (unsigned)(NB1 - 1));
}

__device__ __forceinline__ double blockReduceD(double v, double* dred) {
    int lane = threadIdx.x & 31;
    int wid  = threadIdx.x >> 5;
    #pragma unroll
    for (int o = 16; o > 0; o >>= 1) v += __shfl_down_sync(0xffffffffu, v, o);
    if (lane == 0) dred[wid] = v;
    __syncthreads();
    double r;
    if (wid == 0) {
        r = (lane < BDIM / 32) ? dred[lane] : 0.0;
        #pragma unroll
        for (int o = 16; o > 0; o >>= 1) r += __shfl_down_sync(0xffffffffu, r, o);
        if (lane == 0) dred[0] = r;
    }
    __syncthreads();
    r = dred[0];
    __syncthreads();
    return r;
}

// Find bin b, cnt_gt = count(bins > b) with cnt_gt < k <= cnt_gt + hist[b].
template <int NBINS>
__device__ __forceinline__ void selectBin(const unsigned int* hist, unsigned int* chunk,
                                          unsigned int k, unsigned int* bcast) {
    constexpr int CPT = NBINS / BDIM;
    const int t = threadIdx.x;
    const unsigned base = (unsigned)t * CPT;
    unsigned int ct = 0;
    #pragma unroll
    for (int i = 0; i < CPT; i++) ct += hist[base + i];
    chunk[t] = ct;
    for (int off = 1; off < BDIM; off <<= 1) {
        __syncthreads();
        unsigned int add = (t + off < BDIM) ? chunk[t + off] : 0u;
        __syncthreads();
        chunk[t] += add;
    }
    __syncthreads();
    unsigned int incl = chunk[t];
    unsigned int suf  = incl - ct;
    if (suf < k && k <= incl) {
        unsigned int running = suf;
        #pragma unroll
        for (int i = CPT - 1; i >= 0; i--) {
            unsigned int c = hist[base + i];
            if (running < k && k <= running + c) {
                bcast[0] = base + (unsigned)i;
                bcast[1] = running;
                break;
            }
            running += c;
        }
    }
    __syncthreads();
}

__global__ void __launch_bounds__(BDIM)
k_main(const float* __restrict__ hsi, const float* __restrict__ wp,
       float* __restrict__ out) {
    __shared__ unsigned int s_hist[NB2];    // 20 KB (pass A uses first NB1)
    __shared__ unsigned int s_chunk[BDIM];  // 1 KB
    __shared__ double       s_dred[32];
    __shared__ unsigned int s_bcast[2];
    __shared__ int          s_last;

    const int t = threadIdx.x;
    const int s = blockIdx.x;                 // slice id (b = s/CCH, c = s%CCH)
    const float wv = wp[0];

    const float4* __restrict__ in = reinterpret_cast<const float4*>(hsi + (size_t)s * HW);

    if (t < 2) s_bcast[t] = 0u;
    for (int i = t; i < NB2; i += BDIM) s_hist[i] = 0u;
    __syncthreads();

    // ---- Pass A (light): sampled coarse histogram. 8 chunks of 256 float4 = 8192 elems (1/8).
    #pragma unroll
    for (int m = 0; m < 8; m++) {
        float4 v = in[m * 2048 + t];
        atomicAdd(&s_hist[key1_of(ent_of(v.x * wv))], 1u);
        atomicAdd(&s_hist[key1_of(ent_of(v.y * wv))], 1u);
        atomicAdd(&s_hist[key1_of(ent_of(v.z * wv))], 1u);
        atomicAdd(&s_hist[key1_of(ent_of(v.w * wv))], 1u);
    }
    __syncthreads();

    // ---- Window select from sample (bs +- 2 coarse bins ~= +-15 sigma) ----
    selectBin<NB1>(s_hist, s_chunk, KSUB, s_bcast);
    const unsigned bs  = s_bcast[0];
    const unsigned blo = (bs >= 2) ? bs - 2 : 0u;
    const unsigned bhi = min(bs + 2, (unsigned)(NB1 - 1));
    __syncthreads();

    for (int i = t; i < NB2; i += BDIM) s_hist[i] = 0u;   // clear for exact window hist
    __syncthreads();

    // ---- Pass B (full, exact): Ssum + sum/count above window + window sub-histogram ----
    float a0 = 0.f, a1 = 0.f, a2 = 0.f, a3 = 0.f;   // total-entropy lane sums
    float g0 = 0.f, g1 = 0.f, g2 = 0.f, g3 = 0.f;   // above-window lane sums
    int   cnt = 0;                                   // above-window lane count
    #pragma unroll 4
    for (int i = t; i < HW / 4; i += BDIM) {
        float4 v = in[i];
        float e0 = ent_of(v.x * wv), e1 = ent_of(v.y * wv);
        float e2 = ent_of(v.z * wv), e3 = ent_of(v.w * wv);
        a0 += e0; a1 += e1; a2 += e2; a3 += e3;
        unsigned u0 = __float_as_uint(e0), u1 = __float_as_uint(e1);
        unsigned u2 = __float_as_uint(e2), u3 = __float_as_uint(e3);
        unsigned k0 = min(u0 >> 18, (unsigned)(NB1 - 1));
        unsigned k1 = min(u1 >> 18, (unsigned)(NB1 - 1));
        unsigned k2 = min(u2 >> 18, (unsigned)(NB1 - 1));
        unsigned k3 = min(u3 >> 18, (unsigned)(NB1 - 1));
        if (k0 > bhi) { g0 += e0; cnt++; }
        else if (k0 >= blo) atomicAdd(&s_hist[(k0 - blo) * SUBB + ((u0 >> 8) & (SUBB - 1))], 1u);
        if (k1 > bhi) { g1 += e1; cnt++; }
        else if (k1 >= blo) atomicAdd(&s_hist[(k1 - blo) * SUBB + ((u1 >> 8) & (SUBB - 1))], 1u);
        if (k2 > bhi) { g2 += e2; cnt++; }
        else if (k2 >= blo) atomicAdd(&s_hist[(k2 - blo) * SUBB + ((u2 >> 8) & (SUBB - 1))], 1u);
        if (k3 > bhi) { g3 += e3; cnt++; }
        else if (k3 >= blo) atomicAdd(&s_hist[(k3 - blo) * SUBB + ((u3 >> 8) & (SUBB - 1))], 1u);
    }
    __syncthreads();

    double Ssum = blockReduceD(((double)a0 + (double)a1) + ((double)a2 + (double)a3), s_dred);
    double SGT  = blockReduceD(((double)g0 + (double)g1) + ((double)g2 + (double)g3), s_dred);
    double CGT  = blockReduceD((double)cnt, s_dred);

    // ---- Exact select inside window ----
    const unsigned kp = KSEL - (unsigned)llrint(CGT);   // in [1, window_count]
    selectBin<NB2>(s_hist, s_chunk, kp, s_bcast);
    const unsigned b2      = s_bcast[0];
    const unsigned cnt_gt2 = s_bcast[1];
    __syncthreads();

    // Sum of window bins strictly above b2, midpoint-reconstructed values
    double l2 = 0.0;
    for (int i = t; i < NB2; i += BDIM) {
        unsigned c = s_hist[i];
        if ((unsigned)i > b2 && c) {
            unsigned kg = blo + (unsigned)i / SUBB, sb = (unsigned)i % SUBB;
            l2 += (double)c * (double)__uint_as_float((kg << 18) | (sb << 8) | 128u);
        }
    }
    double SGT2 = blockReduceD(l2, s_dred);

    if (t == 0) {
        unsigned r2 = kp - cnt_gt2;               // elements taken from bin b2
        unsigned kg = blo + b2 / SUBB, sb = b2 % SUBB;
        double mid = (double)__uint_as_float((kg << 18) | (sb << 8) | 128u);
        g_S[s] = Ssum;
        g_T[s] = SGT + SGT2 + (double)r2 * mid;
    }

    // ---- Fused finalization: last CTA reduces 128 channels ----
    __threadfence();
    if (t == 0) {
        unsigned old = atomicAdd(&g_done, 1u);
        s_last = (old == (unsigned)(NSLICE - 1)) ? 1 : 0;
    }
    __syncthreads();
    if (s_last) {
        __shared__ double d[CCH];
        __shared__ double sv[CCH];
        __shared__ int    si[CCH];
        if (t < CCH) {
            double S = 0.0, T = 0.0;
            #pragma unroll
            for (int b = 0; b < BB; b++) {
                S += g_S[b * CCH + t];
                T += g_T[b * CCH + t];
            }
            double mean      = S / ((double)BB * (double)HW);
            double mean_high = T / ((double)BB * (double)KSEL);
            d[t] = 2.0 * (mean_high - mean);
        }
        __syncthreads();
        #pragma unroll
        for (int j = 0; j < 3; j++) {
            if (t < CCH) { sv[t] = d[t]; si[t] = t; }
            __syncthreads();
            #pragma unroll
            for (int off = CCH / 2; off > 0; off >>= 1) {
                if (t < off) {
                    double ov = sv[t + off]; int oi = si[t + off];
                    if (ov > sv[t] || (ov == sv[t] && oi < si[t])) { sv[t] = ov; si[t] = oi; }
                }
                __syncthreads();
            }
            if (t == 0) {
                out[j] = (float)si[0];             // FLOAT32 output: indices as f32 values
                d[si[0]] = -1e300;
            }
            __syncthreads();
        }
        if (t == 0) g_done = 0;                    // reset for next graph replay
    }
}

extern "C" void kernel_launch(void* const* d_in, const int* in_sizes, int n_in,
                              void* d_out, int out_size) {
    // Robust input selection: hsi is the big tensor (16,777,216 elems), w is scalar.
    const float* hsi = (const float*)d_in[0];
    const float* w   = (n_in > 1) ? (const float*)d_in[1] : (const float*)d_in[0];
    if (n_in > 1 && in_sizes[0] < in_sizes[1]) {
        hsi = (const float*)d_in[1];
        w   = (const float*)d_in[0];
    }
    float* out = (float*)d_out;

    k_main<<<NSLICE, BDIM>>>(hsi, w, out);
}